// round 16
// baseline (speedup 1.0000x reference)
#include <cuda_runtime.h>
#include <cuda_bf16.h>
#include <cstdint>
#include <math.h>

// ---------------------------------------------------------------------------
// PatchNCE loss, 4 pyramid layers, stage-batched.
// Unified GEMM core (bf16x3 split HMMA, fp32 accum, cp.async 2-stage
// pipeline) with XOR-swizzled smem tiles (32-half rows, chunk ^= (row>>1)&3).
//   gemm1     <1,4,2>: 128x64 tiles, bias+relu+split-bf16, heavy-first
//   gemm2 ALL <2,1,4>: 32x128 tiles, bias + fused row-L2-norm, ONE kernel
//             (single instantiation; BN=128 >= Co for every layer; layers
//             merged heavy-first so short l0-l2 CTAs backfill l3 latency)
//   scores    <3,4,2>: 128x64 tiles, fused exp-sum + diag
// Gather: 4 channels/thread, float4 patch loads, uint2 stores.
// loss(b,s) = (1 - diag)/tau + log( sum_t exp((v_t - 1)/tau) )
// ---------------------------------------------------------------------------

#define INVTAU 14.285714285714286f

__constant__ int c_cumC[4] = {0, 64, 192, 448};
__constant__ int c_cumZ[4] = {0, 16, 48, 112};
__constant__ int c_cumW[4] = {0, 5120, 25600, 107520};

__device__ __nv_bfloat16 g_fthi[8192 * 960];
__device__ __nv_bfloat16 g_ftlo[8192 * 960];
__device__ __nv_bfloat16 g_hidhi[8192 * 960];
__device__ __nv_bfloat16 g_hidlo[8192 * 960];
__device__ __nv_bfloat16 g_zhi[8192 * 240];
__device__ __nv_bfloat16 g_zlo[8192 * 240];
__device__ __nv_bfloat16 g_whi[435200];
__device__ __nv_bfloat16 g_wlo[435200];
__device__ float         g_esum[16384 * 8];
__device__ float         g_diag[16384];
__device__ float         g_partial[64];

struct InPtrs {
    const float* fq[4];
    const float* fk[4];
    const int*   sid[4];
    const float* w1[4];
    const float* b1[4];
    const float* w2[4];
    const float* b2[4];
};

__device__ __forceinline__ void split_bf16(float x, __nv_bfloat16& h, __nv_bfloat16& l)
{
    h = __float2bfloat16(x);
    l = __float2bfloat16(x - __bfloat162float(h));
}

// ---------------------------------------------------------------------------
// Gather (blocks 0..959, 4 channels/thread) + weight conv (960..2659).
// ---------------------------------------------------------------------------
__global__ __launch_bounds__(256) void gw_all(InPtrs ip)
{
    int b = blockIdx.x;
    if (b >= 960) {   // weight conversion
        b -= 960;
        int l = (b < 20) ? 0 : (b < 100) ? 1 : (b < 420) ? 2 : 3;
        const int wb[4] = {0, 20, 100, 420};
        int C = 64 << l, n1 = C * C;
        int idx = (b - wb[l]) * 256 + threadIdx.x;
        float v = (idx < n1) ? ip.w1[l][idx] : ip.w2[l][idx - n1];
        __nv_bfloat16 hh, ll;
        split_bf16(v, hh, ll);
        g_whi[c_cumW[l] + idx] = hh;
        g_wlo[c_cumW[l] + idx] = ll;
        return;
    }
    int l = (b < 64) ? 0 : (b < 192) ? 1 : (b < 448) ? 2 : 3;
    const int gbase[4] = {0, 64, 192, 448};
    int t = b - gbase[l];
    const int C = 64 << l, H = 256 >> l, W = H, HW = H * W;
    const int TOT = (C << 3) * HW;
    int gi = t * 256 + threadIdx.x;
    int shp = 4 + l;
    int token = gi >> shp;
    int cg = gi & ((1 << shp) - 1);
    int tensor = token >> 9;
    int bs = token & 511;
    int bb = bs >> 6, sample = bs & 63;
    int c0 = cg << 2;

    const float* f = tensor ? ip.fk[l] : ip.fq[l];
    const int* sid = ip.sid[l];
    int h0 = sid[sample * 2 + 0];
    int w0 = sid[sample * 2 + 1];
    int o = w0 & 3;

    float v[4][3][3];
#pragma unroll
    for (int cc = 0; cc < 4; cc++) {
        int plane = (bb * C + c0 + cc) * HW;
#pragma unroll
        for (int r = 0; r < 3; r++) {
            int p = plane + (h0 + r) * W + w0;
            int a = p & ~3;
            float4 q0 = __ldg((const float4*)f + (a >> 2));
            float x0, x1, x2;
            if (o == 0)      { x0 = q0.x; x1 = q0.y; x2 = q0.z; }
            else if (o == 1) { x0 = q0.y; x1 = q0.z; x2 = q0.w; }
            else {
                if (a + 8 <= TOT) {
                    float4 q1 = __ldg((const float4*)f + (a >> 2) + 1);
                    if (o == 2) { x0 = q0.z; x1 = q0.w; x2 = q1.x; }
                    else        { x0 = q0.w; x1 = q1.x; x2 = q1.y; }
                } else {
                    x0 = __ldg(f + p); x1 = __ldg(f + p + 1); x2 = __ldg(f + p + 2);
                }
            }
            v[cc][r][0] = x0; v[cc][r][1] = x1; v[cc][r][2] = x2;
        }
    }

    const int dh[8] = {0, 0, 0, 1, 1, 2, 2, 2};
    const int dw[8] = {0, 1, 2, 0, 2, 0, 1, 2};
    __nv_bfloat16 ph[8][4], pl[8][4];
#pragma unroll
    for (int cc = 0; cc < 4; cc++) {
        float ctr = v[cc][1][1];
#pragma unroll
        for (int nb = 0; nb < 8; nb++) {
            float d = v[cc][dh[nb]][dw[nb]] - ctr;
            split_bf16(d, ph[nb][cc], pl[nb][cc]);
        }
    }

    size_t rowBase = (size_t)8192 * c_cumC[l] +
                     ((size_t)tensor * 4096 + (size_t)bs * 8) * C + c0;
#pragma unroll
    for (int nb = 0; nb < 8; nb++) {
        size_t off = rowBase + (size_t)nb * C;
        *(uint2*)(g_fthi + off) = *(const uint2*)&ph[nb][0];
        *(uint2*)(g_ftlo + off) = *(const uint2*)&pl[nb][0];
    }
}

// ---------------------------------------------------------------------------
// MMA / cp.async primitives
// ---------------------------------------------------------------------------
__device__ __forceinline__ void ldsm4(uint32_t* r, uint32_t saddr)
{
    asm volatile("ldmatrix.sync.aligned.m8n8.x4.shared.b16 {%0,%1,%2,%3}, [%4];"
                 : "=r"(r[0]), "=r"(r[1]), "=r"(r[2]), "=r"(r[3])
                 : "r"(saddr));
}

__device__ __forceinline__ void mma16816(float* c, const uint32_t* a, const uint32_t* b)
{
    asm volatile(
        "mma.sync.aligned.m16n8k16.row.col.f32.bf16.bf16.f32 "
        "{%0,%1,%2,%3}, {%4,%5,%6,%7}, {%8,%9}, {%0,%1,%2,%3};"
        : "+f"(c[0]), "+f"(c[1]), "+f"(c[2]), "+f"(c[3])
        : "r"(a[0]), "r"(a[1]), "r"(a[2]), "r"(a[3]), "r"(b[0]), "r"(b[1]));
}

__device__ __forceinline__ void cpa16(uint32_t dst, const void* src, bool p)
{
    int sz = p ? 16 : 0;
    asm volatile("cp.async.cg.shared.global [%0], [%1], 16, %2;\n"
                 :: "r"(dst), "l"(src), "r"(sz));
}
#define CP_COMMIT() asm volatile("cp.async.commit_group;\n")
#define CP_WAIT0()  asm volatile("cp.async.wait_group 0;\n")
#define CP_WAIT1()  asm volatile("cp.async.wait_group 1;\n")

// Swizzled tile loader: R rows x 32 halfs (four 16B chunks/row).
// Physical chunk = logical chunk ^ ((row>>1)&3). Conflict-free stores+ldsm.
template <int R>
__device__ __forceinline__ void loadT(__nv_bfloat16 (*Ts)[R][32],
    const __nv_bfloat16* hi, const __nv_bfloat16* lo,
    int r0, int Rlim, int K, int kt, int tid)
{
    constexpr int TOTV = R * 4;
#pragma unroll
    for (int i = 0; i < (TOTV + 255) / 256; i++) {
        int it = tid + i * 256;
        if ((TOTV % 256) != 0 && it >= TOTV) break;
        int row = it >> 2, ck = it & 3;
        int sc = ck ^ ((row >> 1) & 3);
        bool p = (r0 + row) < Rlim && (kt + ck * 8) < K;
        size_t off = (size_t)(r0 + row) * K + kt + ck * 8;
        cpa16((uint32_t)__cvta_generic_to_shared(&Ts[0][row][sc * 8]),
              p ? (const void*)(hi + off) : (const void*)hi, p);
        cpa16((uint32_t)__cvta_generic_to_shared(&Ts[1][row][sc * 8]),
              p ? (const void*)(lo + off) : (const void*)lo, p);
    }
}

// ---------------------------------------------------------------------------
// Unified GEMM core. BM=32*MI rows, BN=32*NI cols, BK=32, 8 warps (2m x 4n),
// warp tile (16*MI) x (8*NI). bf16x3 split, 2-stage cp.async pipeline,
// swizzled smem.
// MODE 1: +bias, relu, split-bf16 store.
// MODE 2: +bias, fused row L2-norm, split-bf16 store (requires BN >= N, n0=0).
// MODE 3: scores epilogue -> per-row exp-sum partials + diag.
// ---------------------------------------------------------------------------
template <int MODE, int MI, int NI>
__device__ __forceinline__ void gemm_core(
    const __nv_bfloat16* __restrict__ Ahi, const __nv_bfloat16* __restrict__ Alo,
    const __nv_bfloat16* __restrict__ Bhi, const __nv_bfloat16* __restrict__ Blo,
    const float* __restrict__ bias,
    __nv_bfloat16* __restrict__ Chi, __nv_bfloat16* __restrict__ Clo,
    float* __restrict__ esum, float* __restrict__ diag, int bxi,
    int m0, int n0, int N, int K)
{
    constexpr int BM = 32 * MI;
    constexpr int BN = 32 * NI;

    __shared__ __align__(16) __nv_bfloat16 As[2][2][BM][32];
    __shared__ __align__(16) __nv_bfloat16 Bs[2][2][BN][32];
    __shared__ float s_red[4][BM];
    __shared__ float s_inv[BM];

    const int tid = threadIdx.x, lane = tid & 31, wid = tid >> 5;
    const int wm = wid & 1, wn = wid >> 1;

    float acc[MI][NI][4];
#pragma unroll
    for (int i = 0; i < MI; i++)
#pragma unroll
        for (int j = 0; j < NI; j++)
#pragma unroll
            for (int k = 0; k < 4; k++) acc[i][j][k] = 0.0f;

    const int nk = (K + 31) >> 5;
    loadT<BM>(As[0], Ahi, Alo, m0, 1 << 30, K, 0, tid);
    loadT<BN>(Bs[0], Bhi, Blo, n0, N, K, 0, tid);
    CP_COMMIT();

    int st = 0;
    for (int it = 0; it < nk; it++) {
        if (it + 1 < nk) {
            loadT<BM>(As[st ^ 1], Ahi, Alo, m0, 1 << 30, K, (it + 1) * 32, tid);
            loadT<BN>(Bs[st ^ 1], Bhi, Blo, n0, N, K, (it + 1) * 32, tid);
            CP_COMMIT();
            CP_WAIT1();
        } else {
            CP_WAIT0();
        }
        __syncthreads();

#pragma unroll
        for (int ks = 0; ks < 32; ks += 16) {
            uint32_t ah[MI][4], al[MI][4], bh[2 * NI], bl[2 * NI];
            const int ac = (ks >> 3) + (lane >> 4);          // logical chunk
            const int arow = wm * (16 * MI) + (lane & 15);
#pragma unroll
            for (int mi = 0; mi < MI; mi++) {
                int r = arow + mi * 16;
                int sca = ac ^ ((r >> 1) & 3);
                ldsm4(ah[mi], (uint32_t)__cvta_generic_to_shared(&As[st][0][r][sca * 8]));
                ldsm4(al[mi], (uint32_t)__cvta_generic_to_shared(&As[st][1][r][sca * 8]));
            }
            const int bc = (ks >> 3) + ((lane & 8) >> 3);
#pragma unroll
            for (int nj = 0; nj < NI / 2; nj++) {
                int brow = wn * (8 * NI) + nj * 16 + (lane & 7) + ((lane >> 4) << 3);
                int scb = bc ^ ((brow >> 1) & 3);
                ldsm4(&bh[nj * 4], (uint32_t)__cvta_generic_to_shared(&Bs[st][0][brow][scb * 8]));
                ldsm4(&bl[nj * 4], (uint32_t)__cvta_generic_to_shared(&Bs[st][1][brow][scb * 8]));
            }
#pragma unroll
            for (int mi = 0; mi < MI; mi++)
#pragma unroll
                for (int ni = 0; ni < NI; ni++) {
                    mma16816(acc[mi][ni], ah[mi], &bh[ni * 2]);
                    mma16816(acc[mi][ni], ah[mi], &bl[ni * 2]);
                    mma16816(acc[mi][ni], al[mi], &bh[ni * 2]);
                }
        }
        __syncthreads();
        st ^= 1;
    }

    const int g  = lane >> 2;
    const int tg = (lane & 3) << 1;

    if (MODE == 1) {
#pragma unroll
        for (int mi = 0; mi < MI; mi++)
#pragma unroll
            for (int ni = 0; ni < NI; ni++) {
                int col = n0 + wn * (8 * NI) + ni * 8 + tg;
                if (col >= N) continue;
#pragma unroll
                for (int hf = 0; hf < 2; hf++) {
                    int row = m0 + wm * (16 * MI) + mi * 16 + g + hf * 8;
                    float v0 = fmaxf(acc[mi][ni][hf * 2 + 0] + bias[col], 0.0f);
                    float v1 = fmaxf(acc[mi][ni][hf * 2 + 1] + bias[col + 1], 0.0f);
                    __nv_bfloat16 h0, l0, h1, l1;
                    split_bf16(v0, h0, l0);
                    split_bf16(v1, h1, l1);
                    size_t o = (size_t)row * N + col;
                    Chi[o] = h0; Chi[o + 1] = h1;
                    Clo[o] = l0; Clo[o + 1] = l1;
                }
            }
    } else if (MODE == 2) {
        // Fused norm: bias, row sum(v^2), rsqrt scale, split-store.
#pragma unroll
        for (int mi = 0; mi < MI; mi++)
#pragma unroll
            for (int hf = 0; hf < 2; hf++) {
                int rloc = wm * (16 * MI) + mi * 16 + hf * 8 + g;
                float ss = 0.0f;
#pragma unroll
                for (int ni = 0; ni < NI; ni++) {
                    int col = wn * (8 * NI) + ni * 8 + tg;
                    if (col < N) {
                        float v0 = acc[mi][ni][hf * 2 + 0] + bias[col];
                        float v1 = acc[mi][ni][hf * 2 + 1] + bias[col + 1];
                        acc[mi][ni][hf * 2 + 0] = v0;
                        acc[mi][ni][hf * 2 + 1] = v1;
                        ss += v0 * v0 + v1 * v1;
                    }
                }
                ss += __shfl_xor_sync(0xffffffffu, ss, 1);
                ss += __shfl_xor_sync(0xffffffffu, ss, 2);
                if ((lane & 3) == 0) s_red[wn][rloc] = ss;
            }
        __syncthreads();
        if (tid < BM) {
            float t = s_red[0][tid] + s_red[1][tid] + s_red[2][tid] + s_red[3][tid];
            s_inv[tid] = 1.0f / (sqrtf(t) + 1e-7f);
        }
        __syncthreads();
#pragma unroll
        for (int mi = 0; mi < MI; mi++)
#pragma unroll
            for (int hf = 0; hf < 2; hf++) {
                int rloc = wm * (16 * MI) + mi * 16 + hf * 8 + g;
                float inv = s_inv[rloc];
                int row = m0 + rloc;
#pragma unroll
                for (int ni = 0; ni < NI; ni++) {
                    int col = wn * (8 * NI) + ni * 8 + tg;
                    if (col >= N) continue;
                    float v0 = acc[mi][ni][hf * 2 + 0] * inv;
                    float v1 = acc[mi][ni][hf * 2 + 1] * inv;
                    __nv_bfloat16 h0, l0, h1, l1;
                    split_bf16(v0, h0, l0);
                    split_bf16(v1, h1, l1);
                    size_t o = (size_t)row * N + col;
                    Chi[o] = h0; Chi[o + 1] = h1;
                    Clo[o] = l0; Clo[o + 1] = l1;
                }
            }
    } else {  // MODE 3: fused exp-sum + diag
#pragma unroll
        for (int mi = 0; mi < MI; mi++)
#pragma unroll
            for (int hf = 0; hf < 2; hf++) {
                int rloc = wm * (16 * MI) + mi * 16 + hf * 8 + g;
                int r = m0 + rloc;
                float s = 0.0f;
#pragma unroll
                for (int ni = 0; ni < NI; ni++)
#pragma unroll
                    for (int j = 0; j < 2; j++) {
                        float v = acc[mi][ni][hf * 2 + j];
                        int c = n0 + wn * (8 * NI) + ni * 8 + tg + j;
                        if (c == r) diag[r] = v;
                        s += __expf((v - 1.0f) * INVTAU);
                    }
                s += __shfl_xor_sync(0xffffffffu, s, 1);
                s += __shfl_xor_sync(0xffffffffu, s, 2);
                if ((lane & 3) == 0) s_red[wn][rloc] = s;
            }
        __syncthreads();
        if (tid < BM) {
            float t = s_red[0][tid] + s_red[1][tid] + s_red[2][tid] + s_red[3][tid];
            esum[(size_t)(m0 + tid) * 8 + bxi] = t;
        }
    }
}

// ---------------------------------------------------------------------------
// GEMM1: hid = relu(ft @ w1^T + b1). 128x64 tiles, heavy layers first.
// ---------------------------------------------------------------------------
__global__ __launch_bounds__(256) void gemm1_all(InPtrs ip)
{
    int b = blockIdx.x;
    int l, t;
    if (b < 512)      { l = 3; t = b; }
    else if (b < 768) { l = 2; t = b - 512; }
    else if (b < 896) { l = 1; t = b - 768; }
    else              { l = 0; t = b - 896; }
    int C = 64 << l;
    int tilesX = C >> 6;
    int by = t / tilesX, bx = t % tilesX;
    size_t fo = (size_t)8192 * c_cumC[l];
    gemm_core<1, 4, 2>(g_fthi + fo, g_ftlo + fo,
                       g_whi + c_cumW[l], g_wlo + c_cumW[l], ip.b1[l],
                       g_hidhi + fo, g_hidlo + fo, nullptr, nullptr, 0,
                       by * 128, bx * 64, C, C);
}

// ---------------------------------------------------------------------------
// GEMM2 + fused L2 norm, ALL layers in one <2,1,4> kernel (32x128 tiles).
// Heavy-first: l3 blocks 0..255, l2 256..511, l1 512..767, l0 768..1023.
// BN=128 >= Co for every layer; zero-fill beyond Co via cp.async zfill.
// ---------------------------------------------------------------------------
__global__ __launch_bounds__(256) void gemm2_all(InPtrs ip)
{
    int b = blockIdx.x;
    int l = 3 - (b >> 8);
    int m0 = (b & 255) * 32;
    int C = 64 << l, Co = 16 << l;
    size_t fo = (size_t)8192 * c_cumC[l];
    size_t zo = (size_t)8192 * c_cumZ[l];
    gemm_core<2, 1, 4>(g_hidhi + fo, g_hidlo + fo,
                       g_whi + c_cumW[l] + C * C, g_wlo + c_cumW[l] + C * C,
                       ip.b2[l], g_zhi + zo, g_zlo + zo, nullptr, nullptr, 0,
                       m0, 0, Co, C);
}

// ---------------------------------------------------------------------------
// Scores + fused exp-sum: 8 batch x 4 by x 8 bx = 256 blocks/layer -> 1024.
// ---------------------------------------------------------------------------
__global__ __launch_bounds__(256) void scores_all()
{
    int b = blockIdx.x;
    int l = b >> 8;
    int t = b & 255;
    int batch = t >> 5;
    t &= 31;
    int by = t >> 3, bx = t & 7;
    int Co = 16 << l;
    size_t zb = (size_t)8192 * c_cumZ[l];
    const __nv_bfloat16* qhi = g_zhi + zb + (size_t)batch * 512 * Co;
    const __nv_bfloat16* qlo = g_zlo + zb + (size_t)batch * 512 * Co;
    const __nv_bfloat16* khi = g_zhi + zb + (size_t)(4096 + batch * 512) * Co;
    const __nv_bfloat16* klo = g_zlo + zb + (size_t)(4096 + batch * 512) * Co;
    float* esum = g_esum + (size_t)(l * 8 + batch) * 512 * 8;
    float* diag = g_diag + (size_t)(l * 8 + batch) * 512;
    gemm_core<3, 4, 2>(qhi, qlo, khi, klo, nullptr, nullptr, nullptr,
                       esum, diag, bx, by * 128, bx * 64, 512, Co);
}

// ---------------------------------------------------------------------------
// LSE partial: 64 blocks x 256 rows each. loss = (1-diag)/tau + log(sum8).
// ---------------------------------------------------------------------------
__global__ void lse_partial()
{
    int row = blockIdx.x * 256 + threadIdx.x;
    const float4* e = (const float4*)(g_esum + (size_t)row * 8);
    float4 a = __ldg(e), b = __ldg(e + 1);
    float se = ((a.x + a.y) + (a.z + a.w)) + ((b.x + b.y) + (b.z + b.w));
    float loss = (1.0f - __ldg(g_diag + row)) * INVTAU + logf(se);
    __shared__ float sh[256];
    sh[threadIdx.x] = loss;
    __syncthreads();
    for (int st = 128; st; st >>= 1) {
        if (threadIdx.x < st) sh[threadIdx.x] += sh[threadIdx.x + st];
        __syncthreads();
    }
    if (threadIdx.x == 0) g_partial[blockIdx.x] = sh[0];
}

__global__ void lse_fin(float* __restrict__ out)
{
    __shared__ float sh[64];
    if (threadIdx.x < 64) sh[threadIdx.x] = g_partial[threadIdx.x];
    __syncthreads();
    if (threadIdx.x == 0) {
        float s = 0.0f;
        for (int i = 0; i < 64; i++) s += sh[i];
        out[0] = s / 4096.0f;
    }
}

// ---------------------------------------------------------------------------
extern "C" void kernel_launch(void* const* d_in, const int* in_sizes, int n_in,
                              void* d_out, int out_size)
{
    (void)n_in; (void)out_size;
    bool dict_order = (in_sizes[0] == in_sizes[1]) && (in_sizes[2] == 128);

    InPtrs ip;
    for (int l = 0; l < 4; l++) {
        int ifq, ifk, isid, iw1, ib1, iw2, ib2;
        if (dict_order) {
            int base = 7 * l;
            ifq = base; ifk = base + 1; isid = base + 2;
            iw1 = base + 3; ib1 = base + 4; iw2 = base + 5; ib2 = base + 6;
        } else {
            ifq = l; ifk = 4 + l; isid = 8 + l;
            iw1 = 12 + l * 4; ib1 = iw1 + 1; iw2 = iw1 + 2; ib2 = iw1 + 3;
        }
        ip.fq[l]  = (const float*)d_in[ifq];
        ip.fk[l]  = (const float*)d_in[ifk];
        ip.sid[l] = (const int*)d_in[isid];
        ip.w1[l]  = (const float*)d_in[iw1];
        ip.b1[l]  = (const float*)d_in[ib1];
        ip.w2[l]  = (const float*)d_in[iw2];
        ip.b2[l]  = (const float*)d_in[ib2];
    }

    gw_all<<<2660, 256>>>(ip);
    gemm1_all<<<960, 256>>>(ip);
    gemm2_all<<<1024, 256>>>(ip);
    scores_all<<<1024, 256>>>();
    lse_partial<<<64, 256>>>();
    lse_fin<<<1, 64>>>((float*)d_out);
}

// round 17
// speedup vs baseline: 1.4457x; 1.4457x over previous
#include <cuda_runtime.h>
#include <cuda_bf16.h>
#include <cstdint>
#include <math.h>

// ---------------------------------------------------------------------------
// PatchNCE loss, 4 pyramid layers, stage-batched.  (R15 config — validated
// best — plus split final reduction.)
// Unified GEMM core (bf16x3 split HMMA, fp32 accum, cp.async 2-stage
// pipeline) with XOR-swizzled smem tiles (32-half rows, chunk ^= (row>>1)&3).
//   gemm1         <1,4,2>: 128x64 tiles, bias+relu+split-bf16, heavy-first
//   gemm2 l0-2    <2,2,2>:  64x64 tiles, bias + fused row-L2-norm
//   gemm2 l3      <2,1,4>:  32x128 tiles (256 CTAs), fused norm
//   scores        <3,4,2>: 128x64 tiles, fused exp-sum + diag
// Tile width MUST match N (R9/R16 lesson: wide tiles on small N waste MMA
// work and multiply B traffic).
// Gather: 4 channels/thread, float4 patch loads, uint2 stores.
// loss(b,s) = (1 - diag)/tau + log( sum_t exp((v_t - 1)/tau) )
// ---------------------------------------------------------------------------

#define INVTAU 14.285714285714286f

__constant__ int c_cumC[4] = {0, 64, 192, 448};
__constant__ int c_cumZ[4] = {0, 16, 48, 112};
__constant__ int c_cumW[4] = {0, 5120, 25600, 107520};

__device__ __nv_bfloat16 g_fthi[8192 * 960];
__device__ __nv_bfloat16 g_ftlo[8192 * 960];
__device__ __nv_bfloat16 g_hidhi[8192 * 960];
__device__ __nv_bfloat16 g_hidlo[8192 * 960];
__device__ __nv_bfloat16 g_zhi[8192 * 240];
__device__ __nv_bfloat16 g_zlo[8192 * 240];
__device__ __nv_bfloat16 g_whi[435200];
__device__ __nv_bfloat16 g_wlo[435200];
__device__ float         g_esum[16384 * 8];
__device__ float         g_diag[16384];
__device__ float         g_partial[64];

struct InPtrs {
    const float* fq[4];
    const float* fk[4];
    const int*   sid[4];
    const float* w1[4];
    const float* b1[4];
    const float* w2[4];
    const float* b2[4];
};

__device__ __forceinline__ void split_bf16(float x, __nv_bfloat16& h, __nv_bfloat16& l)
{
    h = __float2bfloat16(x);
    l = __float2bfloat16(x - __bfloat162float(h));
}

// ---------------------------------------------------------------------------
// Gather (blocks 0..959, 4 channels/thread) + weight conv (960..2659).
// ---------------------------------------------------------------------------
__global__ __launch_bounds__(256) void gw_all(InPtrs ip)
{
    int b = blockIdx.x;
    if (b >= 960) {   // weight conversion
        b -= 960;
        int l = (b < 20) ? 0 : (b < 100) ? 1 : (b < 420) ? 2 : 3;
        const int wb[4] = {0, 20, 100, 420};
        int C = 64 << l, n1 = C * C;
        int idx = (b - wb[l]) * 256 + threadIdx.x;
        float v = (idx < n1) ? ip.w1[l][idx] : ip.w2[l][idx - n1];
        __nv_bfloat16 hh, ll;
        split_bf16(v, hh, ll);
        g_whi[c_cumW[l] + idx] = hh;
        g_wlo[c_cumW[l] + idx] = ll;
        return;
    }
    int l = (b < 64) ? 0 : (b < 192) ? 1 : (b < 448) ? 2 : 3;
    const int gbase[4] = {0, 64, 192, 448};
    int t = b - gbase[l];
    const int C = 64 << l, H = 256 >> l, W = H, HW = H * W;
    const int TOT = (C << 3) * HW;
    int gi = t * 256 + threadIdx.x;
    int shp = 4 + l;
    int token = gi >> shp;
    int cg = gi & ((1 << shp) - 1);
    int tensor = token >> 9;
    int bs = token & 511;
    int bb = bs >> 6, sample = bs & 63;
    int c0 = cg << 2;

    const float* f = tensor ? ip.fk[l] : ip.fq[l];
    const int* sid = ip.sid[l];
    int h0 = sid[sample * 2 + 0];
    int w0 = sid[sample * 2 + 1];
    int o = w0 & 3;

    float v[4][3][3];
#pragma unroll
    for (int cc = 0; cc < 4; cc++) {
        int plane = (bb * C + c0 + cc) * HW;
#pragma unroll
        for (int r = 0; r < 3; r++) {
            int p = plane + (h0 + r) * W + w0;
            int a = p & ~3;
            float4 q0 = __ldg((const float4*)f + (a >> 2));
            float x0, x1, x2;
            if (o == 0)      { x0 = q0.x; x1 = q0.y; x2 = q0.z; }
            else if (o == 1) { x0 = q0.y; x1 = q0.z; x2 = q0.w; }
            else {
                if (a + 8 <= TOT) {
                    float4 q1 = __ldg((const float4*)f + (a >> 2) + 1);
                    if (o == 2) { x0 = q0.z; x1 = q0.w; x2 = q1.x; }
                    else        { x0 = q0.w; x1 = q1.x; x2 = q1.y; }
                } else {
                    x0 = __ldg(f + p); x1 = __ldg(f + p + 1); x2 = __ldg(f + p + 2);
                }
            }
            v[cc][r][0] = x0; v[cc][r][1] = x1; v[cc][r][2] = x2;
        }
    }

    const int dh[8] = {0, 0, 0, 1, 1, 2, 2, 2};
    const int dw[8] = {0, 1, 2, 0, 2, 0, 1, 2};
    __nv_bfloat16 ph[8][4], pl[8][4];
#pragma unroll
    for (int cc = 0; cc < 4; cc++) {
        float ctr = v[cc][1][1];
#pragma unroll
        for (int nb = 0; nb < 8; nb++) {
            float d = v[cc][dh[nb]][dw[nb]] - ctr;
            split_bf16(d, ph[nb][cc], pl[nb][cc]);
        }
    }

    size_t rowBase = (size_t)8192 * c_cumC[l] +
                     ((size_t)tensor * 4096 + (size_t)bs * 8) * C + c0;
#pragma unroll
    for (int nb = 0; nb < 8; nb++) {
        size_t off = rowBase + (size_t)nb * C;
        *(uint2*)(g_fthi + off) = *(const uint2*)&ph[nb][0];
        *(uint2*)(g_ftlo + off) = *(const uint2*)&pl[nb][0];
    }
}

// ---------------------------------------------------------------------------
// MMA / cp.async primitives
// ---------------------------------------------------------------------------
__device__ __forceinline__ void ldsm4(uint32_t* r, uint32_t saddr)
{
    asm volatile("ldmatrix.sync.aligned.m8n8.x4.shared.b16 {%0,%1,%2,%3}, [%4];"
                 : "=r"(r[0]), "=r"(r[1]), "=r"(r[2]), "=r"(r[3])
                 : "r"(saddr));
}

__device__ __forceinline__ void mma16816(float* c, const uint32_t* a, const uint32_t* b)
{
    asm volatile(
        "mma.sync.aligned.m16n8k16.row.col.f32.bf16.bf16.f32 "
        "{%0,%1,%2,%3}, {%4,%5,%6,%7}, {%8,%9}, {%0,%1,%2,%3};"
        : "+f"(c[0]), "+f"(c[1]), "+f"(c[2]), "+f"(c[3])
        : "r"(a[0]), "r"(a[1]), "r"(a[2]), "r"(a[3]), "r"(b[0]), "r"(b[1]));
}

__device__ __forceinline__ void cpa16(uint32_t dst, const void* src, bool p)
{
    int sz = p ? 16 : 0;
    asm volatile("cp.async.cg.shared.global [%0], [%1], 16, %2;\n"
                 :: "r"(dst), "l"(src), "r"(sz));
}
#define CP_COMMIT() asm volatile("cp.async.commit_group;\n")
#define CP_WAIT0()  asm volatile("cp.async.wait_group 0;\n")
#define CP_WAIT1()  asm volatile("cp.async.wait_group 1;\n")

// Swizzled tile loader: R rows x 32 halfs (four 16B chunks/row).
// Physical chunk = logical chunk ^ ((row>>1)&3). Conflict-free stores+ldsm.
template <int R>
__device__ __forceinline__ void loadT(__nv_bfloat16 (*Ts)[R][32],
    const __nv_bfloat16* hi, const __nv_bfloat16* lo,
    int r0, int Rlim, int K, int kt, int tid)
{
    constexpr int TOTV = R * 4;
#pragma unroll
    for (int i = 0; i < (TOTV + 255) / 256; i++) {
        int it = tid + i * 256;
        if ((TOTV % 256) != 0 && it >= TOTV) break;
        int row = it >> 2, ck = it & 3;
        int sc = ck ^ ((row >> 1) & 3);
        bool p = (r0 + row) < Rlim && (kt + ck * 8) < K;
        size_t off = (size_t)(r0 + row) * K + kt + ck * 8;
        cpa16((uint32_t)__cvta_generic_to_shared(&Ts[0][row][sc * 8]),
              p ? (const void*)(hi + off) : (const void*)hi, p);
        cpa16((uint32_t)__cvta_generic_to_shared(&Ts[1][row][sc * 8]),
              p ? (const void*)(lo + off) : (const void*)lo, p);
    }
}

// ---------------------------------------------------------------------------
// Unified GEMM core. BM=32*MI rows, BN=32*NI cols, BK=32, 8 warps (2m x 4n),
// warp tile (16*MI) x (8*NI). bf16x3 split, 2-stage cp.async pipeline,
// swizzled smem.
// MODE 1: +bias, relu, split-bf16 store.
// MODE 2: +bias, fused row L2-norm, split-bf16 store (requires BN >= N, n0=0).
// MODE 3: scores epilogue -> per-row exp-sum partials + diag.
// ---------------------------------------------------------------------------
template <int MODE, int MI, int NI>
__device__ __forceinline__ void gemm_core(
    const __nv_bfloat16* __restrict__ Ahi, const __nv_bfloat16* __restrict__ Alo,
    const __nv_bfloat16* __restrict__ Bhi, const __nv_bfloat16* __restrict__ Blo,
    const float* __restrict__ bias,
    __nv_bfloat16* __restrict__ Chi, __nv_bfloat16* __restrict__ Clo,
    float* __restrict__ esum, float* __restrict__ diag, int bxi,
    int m0, int n0, int N, int K)
{
    constexpr int BM = 32 * MI;
    constexpr int BN = 32 * NI;

    __shared__ __align__(16) __nv_bfloat16 As[2][2][BM][32];
    __shared__ __align__(16) __nv_bfloat16 Bs[2][2][BN][32];
    __shared__ float s_red[4][BM];
    __shared__ float s_inv[BM];

    const int tid = threadIdx.x, lane = tid & 31, wid = tid >> 5;
    const int wm = wid & 1, wn = wid >> 1;

    float acc[MI][NI][4];
#pragma unroll
    for (int i = 0; i < MI; i++)
#pragma unroll
        for (int j = 0; j < NI; j++)
#pragma unroll
            for (int k = 0; k < 4; k++) acc[i][j][k] = 0.0f;

    const int nk = (K + 31) >> 5;
    loadT<BM>(As[0], Ahi, Alo, m0, 1 << 30, K, 0, tid);
    loadT<BN>(Bs[0], Bhi, Blo, n0, N, K, 0, tid);
    CP_COMMIT();

    int st = 0;
    for (int it = 0; it < nk; it++) {
        if (it + 1 < nk) {
            loadT<BM>(As[st ^ 1], Ahi, Alo, m0, 1 << 30, K, (it + 1) * 32, tid);
            loadT<BN>(Bs[st ^ 1], Bhi, Blo, n0, N, K, (it + 1) * 32, tid);
            CP_COMMIT();
            CP_WAIT1();
        } else {
            CP_WAIT0();
        }
        __syncthreads();

#pragma unroll
        for (int ks = 0; ks < 32; ks += 16) {
            uint32_t ah[MI][4], al[MI][4], bh[2 * NI], bl[2 * NI];
            const int ac = (ks >> 3) + (lane >> 4);          // logical chunk
            const int arow = wm * (16 * MI) + (lane & 15);
#pragma unroll
            for (int mi = 0; mi < MI; mi++) {
                int r = arow + mi * 16;
                int sca = ac ^ ((r >> 1) & 3);
                ldsm4(ah[mi], (uint32_t)__cvta_generic_to_shared(&As[st][0][r][sca * 8]));
                ldsm4(al[mi], (uint32_t)__cvta_generic_to_shared(&As[st][1][r][sca * 8]));
            }
            const int bc = (ks >> 3) + ((lane & 8) >> 3);
#pragma unroll
            for (int nj = 0; nj < NI / 2; nj++) {
                int brow = wn * (8 * NI) + nj * 16 + (lane & 7) + ((lane >> 4) << 3);
                int scb = bc ^ ((brow >> 1) & 3);
                ldsm4(&bh[nj * 4], (uint32_t)__cvta_generic_to_shared(&Bs[st][0][brow][scb * 8]));
                ldsm4(&bl[nj * 4], (uint32_t)__cvta_generic_to_shared(&Bs[st][1][brow][scb * 8]));
            }
#pragma unroll
            for (int mi = 0; mi < MI; mi++)
#pragma unroll
                for (int ni = 0; ni < NI; ni++) {
                    mma16816(acc[mi][ni], ah[mi], &bh[ni * 2]);
                    mma16816(acc[mi][ni], ah[mi], &bl[ni * 2]);
                    mma16816(acc[mi][ni], al[mi], &bh[ni * 2]);
                }
        }
        __syncthreads();
        st ^= 1;
    }

    const int g  = lane >> 2;
    const int tg = (lane & 3) << 1;

    if (MODE == 1) {
#pragma unroll
        for (int mi = 0; mi < MI; mi++)
#pragma unroll
            for (int ni = 0; ni < NI; ni++) {
                int col = n0 + wn * (8 * NI) + ni * 8 + tg;
                if (col >= N) continue;
#pragma unroll
                for (int hf = 0; hf < 2; hf++) {
                    int row = m0 + wm * (16 * MI) + mi * 16 + g + hf * 8;
                    float v0 = fmaxf(acc[mi][ni][hf * 2 + 0] + bias[col], 0.0f);
                    float v1 = fmaxf(acc[mi][ni][hf * 2 + 1] + bias[col + 1], 0.0f);
                    __nv_bfloat16 h0, l0, h1, l1;
                    split_bf16(v0, h0, l0);
                    split_bf16(v1, h1, l1);
                    size_t o = (size_t)row * N + col;
                    Chi[o] = h0; Chi[o + 1] = h1;
                    Clo[o] = l0; Clo[o + 1] = l1;
                }
            }
    } else if (MODE == 2) {
        // Fused norm: bias, row sum(v^2), rsqrt scale, split-store.
#pragma unroll
        for (int mi = 0; mi < MI; mi++)
#pragma unroll
            for (int hf = 0; hf < 2; hf++) {
                int rloc = wm * (16 * MI) + mi * 16 + hf * 8 + g;
                float ss = 0.0f;
#pragma unroll
                for (int ni = 0; ni < NI; ni++) {
                    int col = wn * (8 * NI) + ni * 8 + tg;
                    if (col < N) {
                        float v0 = acc[mi][ni][hf * 2 + 0] + bias[col];
                        float v1 = acc[mi][ni][hf * 2 + 1] + bias[col + 1];
                        acc[mi][ni][hf * 2 + 0] = v0;
                        acc[mi][ni][hf * 2 + 1] = v1;
                        ss += v0 * v0 + v1 * v1;
                    }
                }
                ss += __shfl_xor_sync(0xffffffffu, ss, 1);
                ss += __shfl_xor_sync(0xffffffffu, ss, 2);
                if ((lane & 3) == 0) s_red[wn][rloc] = ss;
            }
        __syncthreads();
        if (tid < BM) {
            float t = s_red[0][tid] + s_red[1][tid] + s_red[2][tid] + s_red[3][tid];
            s_inv[tid] = 1.0f / (sqrtf(t) + 1e-7f);
        }
        __syncthreads();
#pragma unroll
        for (int mi = 0; mi < MI; mi++)
#pragma unroll
            for (int hf = 0; hf < 2; hf++) {
                int rloc = wm * (16 * MI) + mi * 16 + hf * 8 + g;
                float inv = s_inv[rloc];
                int row = m0 + rloc;
#pragma unroll
                for (int ni = 0; ni < NI; ni++) {
                    int col = wn * (8 * NI) + ni * 8 + tg;
                    if (col >= N) continue;
                    float v0 = acc[mi][ni][hf * 2 + 0] * inv;
                    float v1 = acc[mi][ni][hf * 2 + 1] * inv;
                    __nv_bfloat16 h0, l0, h1, l1;
                    split_bf16(v0, h0, l0);
                    split_bf16(v1, h1, l1);
                    size_t o = (size_t)row * N + col;
                    Chi[o] = h0; Chi[o + 1] = h1;
                    Clo[o] = l0; Clo[o + 1] = l1;
                }
            }
    } else {  // MODE 3: fused exp-sum + diag
#pragma unroll
        for (int mi = 0; mi < MI; mi++)
#pragma unroll
            for (int hf = 0; hf < 2; hf++) {
                int rloc = wm * (16 * MI) + mi * 16 + hf * 8 + g;
                int r = m0 + rloc;
                float s = 0.0f;
#pragma unroll
                for (int ni = 0; ni < NI; ni++)
#pragma unroll
                    for (int j = 0; j < 2; j++) {
                        float v = acc[mi][ni][hf * 2 + j];
                        int c = n0 + wn * (8 * NI) + ni * 8 + tg + j;
                        if (c == r) diag[r] = v;
                        s += __expf((v - 1.0f) * INVTAU);
                    }
                s += __shfl_xor_sync(0xffffffffu, s, 1);
                s += __shfl_xor_sync(0xffffffffu, s, 2);
                if ((lane & 3) == 0) s_red[wn][rloc] = s;
            }
        __syncthreads();
        if (tid < BM) {
            float t = s_red[0][tid] + s_red[1][tid] + s_red[2][tid] + s_red[3][tid];
            esum[(size_t)(m0 + tid) * 8 + bxi] = t;
        }
    }
}

// ---------------------------------------------------------------------------
// GEMM1: hid = relu(ft @ w1^T + b1). 128x64 tiles, heavy layers first.
// ---------------------------------------------------------------------------
__global__ __launch_bounds__(256) void gemm1_all(InPtrs ip)
{
    int b = blockIdx.x;
    int l, t;
    if (b < 512)      { l = 3; t = b; }
    else if (b < 768) { l = 2; t = b - 512; }
    else if (b < 896) { l = 1; t = b - 768; }
    else              { l = 0; t = b - 896; }
    int C = 64 << l;
    int tilesX = C >> 6;
    int by = t / tilesX, bx = t % tilesX;
    size_t fo = (size_t)8192 * c_cumC[l];
    gemm_core<1, 4, 2>(g_fthi + fo, g_ftlo + fo,
                       g_whi + c_cumW[l], g_wlo + c_cumW[l], ip.b1[l],
                       g_hidhi + fo, g_hidlo + fo, nullptr, nullptr, 0,
                       by * 128, bx * 64, C, C);
}

// ---------------------------------------------------------------------------
// GEMM2 + fused L2 norm, layers 0-2 (single <2,2,2> instantiation).
// Heavy-first: l2 blocks 0..127, l1 128..255, l0 256..383.
// ---------------------------------------------------------------------------
__global__ __launch_bounds__(256) void gemm2_small_all(InPtrs ip)
{
    int b = blockIdx.x;
    int l = 2 - (b >> 7);
    int m0 = (b & 127) * 64;
    int C = 64 << l, Co = 16 << l;
    size_t fo = (size_t)8192 * c_cumC[l];
    size_t zo = (size_t)8192 * c_cumZ[l];
    gemm_core<2, 2, 2>(g_hidhi + fo, g_hidlo + fo,
                       g_whi + c_cumW[l] + C * C, g_wlo + c_cumW[l] + C * C,
                       ip.b2[l], g_zhi + zo, g_zlo + zo, nullptr, nullptr, 0,
                       m0, 0, Co, C);
}

// ---------------------------------------------------------------------------
// GEMM2 + fused L2 norm, layer 3: <2,1,4> 32x128 tiles -> 256 CTAs.
// ---------------------------------------------------------------------------
__global__ __launch_bounds__(256) void gemm2_l3_all(InPtrs ip)
{
    int m0 = blockIdx.x * 32;
    size_t fo = (size_t)8192 * c_cumC[3];
    size_t zo = (size_t)8192 * c_cumZ[3];
    gemm_core<2, 1, 4>(g_hidhi + fo, g_hidlo + fo,
                       g_whi + c_cumW[3] + 512 * 512, g_wlo + c_cumW[3] + 512 * 512,
                       ip.b2[3], g_zhi + zo, g_zlo + zo, nullptr, nullptr, 0,
                       m0, 0, 128, 512);
}

// ---------------------------------------------------------------------------
// Scores + fused exp-sum: 8 batch x 4 by x 8 bx = 256 blocks/layer -> 1024.
// ---------------------------------------------------------------------------
__global__ __launch_bounds__(256) void scores_all()
{
    int b = blockIdx.x;
    int l = b >> 8;
    int t = b & 255;
    int batch = t >> 5;
    t &= 31;
    int by = t >> 3, bx = t & 7;
    int Co = 16 << l;
    size_t zb = (size_t)8192 * c_cumZ[l];
    const __nv_bfloat16* qhi = g_zhi + zb + (size_t)batch * 512 * Co;
    const __nv_bfloat16* qlo = g_zlo + zb + (size_t)batch * 512 * Co;
    const __nv_bfloat16* khi = g_zhi + zb + (size_t)(4096 + batch * 512) * Co;
    const __nv_bfloat16* klo = g_zlo + zb + (size_t)(4096 + batch * 512) * Co;
    float* esum = g_esum + (size_t)(l * 8 + batch) * 512 * 8;
    float* diag = g_diag + (size_t)(l * 8 + batch) * 512;
    gemm_core<3, 4, 2>(qhi, qlo, khi, klo, nullptr, nullptr, nullptr,
                       esum, diag, bx, by * 128, bx * 64, 512, Co);
}

// ---------------------------------------------------------------------------
// LSE partial: 64 blocks x 256 rows each. loss = (1-diag)/tau + log(sum8).
// ---------------------------------------------------------------------------
__global__ void lse_partial()
{
    int row = blockIdx.x * 256 + threadIdx.x;
    const float4* e = (const float4*)(g_esum + (size_t)row * 8);
    float4 a = __ldg(e), b = __ldg(e + 1);
    float se = ((a.x + a.y) + (a.z + a.w)) + ((b.x + b.y) + (b.z + b.w));
    float loss = (1.0f - __ldg(g_diag + row)) * INVTAU + logf(se);
    __shared__ float sh[256];
    sh[threadIdx.x] = loss;
    __syncthreads();
    for (int st = 128; st; st >>= 1) {
        if (threadIdx.x < st) sh[threadIdx.x] += sh[threadIdx.x + st];
        __syncthreads();
    }
    if (threadIdx.x == 0) g_partial[blockIdx.x] = sh[0];
}

__global__ void lse_fin(float* __restrict__ out)
{
    __shared__ float sh[64];
    if (threadIdx.x < 64) sh[threadIdx.x] = g_partial[threadIdx.x];
    __syncthreads();
    if (threadIdx.x == 0) {
        float s = 0.0f;
        for (int i = 0; i < 64; i++) s += sh[i];
        out[0] = s / 4096.0f;
    }
}

// ---------------------------------------------------------------------------
extern "C" void kernel_launch(void* const* d_in, const int* in_sizes, int n_in,
                              void* d_out, int out_size)
{
    (void)n_in; (void)out_size;
    bool dict_order = (in_sizes[0] == in_sizes[1]) && (in_sizes[2] == 128);

    InPtrs ip;
    for (int l = 0; l < 4; l++) {
        int ifq, ifk, isid, iw1, ib1, iw2, ib2;
        if (dict_order) {
            int base = 7 * l;
            ifq = base; ifk = base + 1; isid = base + 2;
            iw1 = base + 3; ib1 = base + 4; iw2 = base + 5; ib2 = base + 6;
        } else {
            ifq = l; ifk = 4 + l; isid = 8 + l;
            iw1 = 12 + l * 4; ib1 = iw1 + 1; iw2 = iw1 + 2; ib2 = iw1 + 3;
        }
        ip.fq[l]  = (const float*)d_in[ifq];
        ip.fk[l]  = (const float*)d_in[ifk];
        ip.sid[l] = (const int*)d_in[isid];
        ip.w1[l]  = (const float*)d_in[iw1];
        ip.b1[l]  = (const float*)d_in[ib1];
        ip.w2[l]  = (const float*)d_in[iw2];
        ip.b2[l]  = (const float*)d_in[ib2];
    }

    gw_all<<<2660, 256>>>(ip);
    gemm1_all<<<960, 256>>>(ip);
    gemm2_small_all<<<384, 256>>>(ip);
    gemm2_l3_all<<<256, 256>>>(ip);
    scores_all<<<1024, 256>>>();
    lse_partial<<<64, 256>>>();
    lse_fin<<<1, 64>>>((float*)d_out);
}